// round 1
// baseline (speedup 1.0000x reference)
#include <cuda_runtime.h>
#include <cuda_bf16.h>
#include <math.h>

#define L_SEQ 700
#define D_DIM 512
#define B_SZ  64
#define TL 128
#define TM 128
#define TK 16
#define INV_TEMP 0.04419417382415922f  // 1/sqrt(512)

// Scratch for column-mean of attn: w[b, m] (padded stride 704)
__device__ float g_w[B_SZ * 704];

// ---------------------------------------------------------------------------
// Kernel 1: per (batch, m-tile) compute w[b,m] = (1/700) * sum_l tanh(G[l,m]/TEMP)*mask[l,m]
// Classic 128x128x16 register-blocked fp32 GEMM; the 128x128 tile is consumed
// immediately (tanh*mask + column reduction) so nothing big is materialized.
// ---------------------------------------------------------------------------
__global__ __launch_bounds__(256, 2) void attn_colsum_kernel(
    const float* __restrict__ enc, const float* __restrict__ mask) {
  const int b  = blockIdx.y;
  const int m0 = blockIdx.x * TM;
  __shared__ float As[TK][TL];
  __shared__ float Bs[TK][TM];
  const float* encB  = enc  + (size_t)b * L_SEQ * D_DIM;
  const float* maskB = mask + (size_t)b * L_SEQ * L_SEQ;
  const int t  = threadIdx.x;
  const int tx = t & 15;
  const int ty = t >> 4;

  float colsum[8];
#pragma unroll
  for (int j = 0; j < 8; j++) colsum[j] = 0.f;

  for (int l0 = 0; l0 < L_SEQ; l0 += TL) {
    float acc[8][8];
#pragma unroll
    for (int i = 0; i < 8; i++)
#pragma unroll
      for (int j = 0; j < 8; j++) acc[i][j] = 0.f;

    for (int k0 = 0; k0 < D_DIM; k0 += TK) {
      // Load 128x16 tiles of A (rows l) and B (rows m), K-major in smem.
#pragma unroll
      for (int i = 0; i < 2; i++) {
        int slot = t + i * 256;      // 0..511
        int row  = slot >> 2;        // 0..127
        int seg  = slot & 3;         // float4 segment within the 16-wide k slab
        int l = l0 + row;
        float4 va = make_float4(0.f, 0.f, 0.f, 0.f);
        if (l < L_SEQ) va = *(const float4*)(encB + (size_t)l * D_DIM + k0 + seg * 4);
        As[seg * 4 + 0][row] = va.x;
        As[seg * 4 + 1][row] = va.y;
        As[seg * 4 + 2][row] = va.z;
        As[seg * 4 + 3][row] = va.w;
        int m = m0 + row;
        float4 vb = make_float4(0.f, 0.f, 0.f, 0.f);
        if (m < L_SEQ) vb = *(const float4*)(encB + (size_t)m * D_DIM + k0 + seg * 4);
        Bs[seg * 4 + 0][row] = vb.x;
        Bs[seg * 4 + 1][row] = vb.y;
        Bs[seg * 4 + 2][row] = vb.z;
        Bs[seg * 4 + 3][row] = vb.w;
      }
      __syncthreads();
#pragma unroll
      for (int kk = 0; kk < TK; kk++) {
        float4 a0 = *(const float4*)&As[kk][ty * 4];
        float4 a1 = *(const float4*)&As[kk][64 + ty * 4];
        float4 b0 = *(const float4*)&Bs[kk][tx * 4];
        float4 b1 = *(const float4*)&Bs[kk][64 + tx * 4];
        float ra[8] = {a0.x, a0.y, a0.z, a0.w, a1.x, a1.y, a1.z, a1.w};
        float rb[8] = {b0.x, b0.y, b0.z, b0.w, b1.x, b1.y, b1.z, b1.w};
#pragma unroll
        for (int i = 0; i < 8; i++)
#pragma unroll
          for (int j = 0; j < 8; j++) acc[i][j] += ra[i] * rb[j];
      }
      __syncthreads();
    }

    // Consume the tile: tanh(G/TEMP)*mask, accumulate column sums over l.
#pragma unroll
    for (int i = 0; i < 8; i++) {
      int l = l0 + ((i < 4) ? (ty * 4 + i) : (64 + ty * 4 + (i - 4)));
      if (l < L_SEQ) {
        const float* mrow = maskB + (size_t)l * L_SEQ;
#pragma unroll
        for (int j = 0; j < 8; j++) {
          int m = m0 + ((j < 4) ? (tx * 4 + j) : (64 + tx * 4 + (j - 4)));
          if (m < L_SEQ) {
            colsum[j] += tanhf(acc[i][j] * INV_TEMP) * mrow[m];
          }
        }
      }
    }
  }

  // Cross-thread reduction over the 16 ty-groups sharing each column.
#pragma unroll
  for (int j = 0; j < 8; j++) {
    int lc = (j < 4) ? (tx * 4 + j) : (64 + tx * 4 + (j - 4));
    As[ty][lc] = colsum[j];
  }
  __syncthreads();
  if (t < TM) {
    float s = 0.f;
#pragma unroll
    for (int r = 0; r < TK; r++) s += As[r][t];
    int m = m0 + t;
    if (m < L_SEQ) g_w[b * 704 + m] = s * (1.0f / 700.0f);
  }
}

// ---------------------------------------------------------------------------
// Kernel 2: one block per batch. One streaming pass over enc[b] computes both
// seq1[b,d] = sum_m w[b,m] enc[b,m,d]  and the three shifted c3-weighted row
// sums T[di][d]; then the 3x3 stencil gives seq2 and we emit
// tanh(user + seq1/2 + seq2*2).
// ---------------------------------------------------------------------------
__global__ __launch_bounds__(512) void finalize_kernel(
    const float* __restrict__ user, const float* __restrict__ enc,
    const float* __restrict__ conv_w, const float* __restrict__ conv_b,
    const float* __restrict__ conv3_w, const float* __restrict__ conv3_b,
    float* __restrict__ out) {
  const int b = blockIdx.x;
  const int d = threadIdx.x;  // 0..511

  __shared__ float sc3p[704];   // sc3p[0]=0, sc3p[1+h]=c3[h], tail zeros
  __shared__ float sw[704];
  __shared__ float T[3][514];   // padded stencil buffers (index d+1)

  for (int i = d; i < 704; i += 512) {
    sc3p[i] = 0.f;
    sw[i] = (i < L_SEQ) ? g_w[b * 704 + i] : 0.f;
  }
  __syncthreads();
  for (int i = d; i < L_SEQ; i += 512) sc3p[i + 1] = conv3_w[i];
  __syncthreads();

  // sum of c3 (for the conv_b pass-through term); 4-way partial to break the chain
  float cs0 = 0.f, cs1 = 0.f, cs2 = 0.f, cs3 = 0.f;
  for (int h = 0; h < L_SEQ; h += 4) {
    cs0 += sc3p[h + 1];
    cs1 += sc3p[h + 2];
    cs2 += sc3p[h + 3];
    cs3 += (h + 4 <= L_SEQ) ? sc3p[h + 4] : 0.f;
  }
  float c3sum = cs0 + cs1 + cs2 + cs3;

  const float* e = enc + (size_t)b * L_SEQ * D_DIM + d;
  float s1 = 0.f, tm1 = 0.f, t0 = 0.f, tp1 = 0.f;
#pragma unroll 4
  for (int h = 0; h < L_SEQ; h++) {
    float v = e[(size_t)h * D_DIM];
    s1  += sw[h] * v;
    tm1 += sc3p[h + 2] * v;   // c3[h+1]  (di = -1)
    t0  += sc3p[h + 1] * v;   // c3[h]    (di =  0)
    tp1 += sc3p[h]     * v;   // c3[h-1]  (di = +1)
  }

  T[0][d + 1] = tm1;
  T[1][d + 1] = t0;
  T[2][d + 1] = tp1;
  if (d == 0) {
    T[0][0] = 0.f; T[1][0] = 0.f; T[2][0] = 0.f;
    T[0][513] = 0.f; T[1][513] = 0.f; T[2][513] = 0.f;
  }
  __syncthreads();

  float W[3][3];
#pragma unroll
  for (int i = 0; i < 3; i++)
#pragma unroll
    for (int j = 0; j < 3; j++) W[i][j] = conv_w[i * 3 + j];

  float seq2 = conv3_b[0] + conv_b[0] * c3sum;
#pragma unroll
  for (int di = 0; di < 3; di++)
#pragma unroll
    for (int dj = 0; dj < 3; dj++)
      seq2 += W[di][dj] * T[di][d + dj];

  out[b * D_DIM + d] = tanhf(user[b * D_DIM + d] + s1 * 0.5f + seq2 * 2.0f);
}

extern "C" void kernel_launch(void* const* d_in, const int* in_sizes, int n_in,
                              void* d_out, int out_size) {
  const float* user    = (const float*)d_in[0];
  // d_in[1] = embeddings (22,512) — unused by the reference
  const float* enc     = (const float*)d_in[2];
  const float* mask    = (const float*)d_in[3];
  const float* conv_w  = (const float*)d_in[4];
  const float* conv_b  = (const float*)d_in[5];
  const float* conv3_w = (const float*)d_in[6];
  const float* conv3_b = (const float*)d_in[7];
  float* out = (float*)d_out;

  dim3 grid1((L_SEQ + TM - 1) / TM, B_SZ);   // (6, 64)
  attn_colsum_kernel<<<grid1, 256>>>(enc, mask);
  finalize_kernel<<<B_SZ, 512>>>(user, enc, conv_w, conv_b, conv3_w, conv3_b, out);
}

// round 2
// speedup vs baseline: 1.0023x; 1.0023x over previous
#include <cuda_runtime.h>
#include <cuda_bf16.h>
#include <math.h>

#define L_SEQ 700
#define D_DIM 512
#define B_SZ  64
#define TL 128
#define TM 128
#define TK 16
#define INV_TEMP 0.04419417382415922f  // 1/sqrt(512)

// Scratch for column-mean of attn: w[b, m] (padded stride 704)
__device__ float g_w[B_SZ * 704];

// ---------------------------------------------------------------------------
// Kernel 1: per (batch, m-tile) compute w[b,m] = (1/700) * sum_l tanh(G[l,m]/TEMP)*mask[l,m]
// Classic 128x128x16 register-blocked fp32 GEMM; the 128x128 tile is consumed
// immediately (tanh*mask + column reduction) so nothing big is materialized.
// ---------------------------------------------------------------------------
__global__ __launch_bounds__(256, 2) void attn_colsum_kernel(
    const float* __restrict__ enc, const float* __restrict__ mask) {
  const int b  = blockIdx.y;
  const int m0 = blockIdx.x * TM;
  __shared__ float As[TK][TL];
  __shared__ float Bs[TK][TM];
  const float* encB  = enc  + (size_t)b * L_SEQ * D_DIM;
  const float* maskB = mask + (size_t)b * L_SEQ * L_SEQ;
  const int t  = threadIdx.x;
  const int tx = t & 15;
  const int ty = t >> 4;

  float colsum[8];
#pragma unroll
  for (int j = 0; j < 8; j++) colsum[j] = 0.f;

  for (int l0 = 0; l0 < L_SEQ; l0 += TL) {
    float acc[8][8];
#pragma unroll
    for (int i = 0; i < 8; i++)
#pragma unroll
      for (int j = 0; j < 8; j++) acc[i][j] = 0.f;

    for (int k0 = 0; k0 < D_DIM; k0 += TK) {
      // Load 128x16 tiles of A (rows l) and B (rows m), K-major in smem.
#pragma unroll
      for (int i = 0; i < 2; i++) {
        int slot = t + i * 256;      // 0..511
        int row  = slot >> 2;        // 0..127
        int seg  = slot & 3;         // float4 segment within the 16-wide k slab
        int l = l0 + row;
        float4 va = make_float4(0.f, 0.f, 0.f, 0.f);
        if (l < L_SEQ) va = *(const float4*)(encB + (size_t)l * D_DIM + k0 + seg * 4);
        As[seg * 4 + 0][row] = va.x;
        As[seg * 4 + 1][row] = va.y;
        As[seg * 4 + 2][row] = va.z;
        As[seg * 4 + 3][row] = va.w;
        int m = m0 + row;
        float4 vb = make_float4(0.f, 0.f, 0.f, 0.f);
        if (m < L_SEQ) vb = *(const float4*)(encB + (size_t)m * D_DIM + k0 + seg * 4);
        Bs[seg * 4 + 0][row] = vb.x;
        Bs[seg * 4 + 1][row] = vb.y;
        Bs[seg * 4 + 2][row] = vb.z;
        Bs[seg * 4 + 3][row] = vb.w;
      }
      __syncthreads();
#pragma unroll
      for (int kk = 0; kk < TK; kk++) {
        float4 a0 = *(const float4*)&As[kk][ty * 4];
        float4 a1 = *(const float4*)&As[kk][64 + ty * 4];
        float4 b0 = *(const float4*)&Bs[kk][tx * 4];
        float4 b1 = *(const float4*)&Bs[kk][64 + tx * 4];
        float ra[8] = {a0.x, a0.y, a0.z, a0.w, a1.x, a1.y, a1.z, a1.w};
        float rb[8] = {b0.x, b0.y, b0.z, b0.w, b1.x, b1.y, b1.z, b1.w};
#pragma unroll
        for (int i = 0; i < 8; i++)
#pragma unroll
          for (int j = 0; j < 8; j++) acc[i][j] += ra[i] * rb[j];
      }
      __syncthreads();
    }

    // Consume the tile: tanh(G/TEMP)*mask, accumulate column sums over l.
#pragma unroll
    for (int i = 0; i < 8; i++) {
      int l = l0 + ((i < 4) ? (ty * 4 + i) : (64 + ty * 4 + (i - 4)));
      if (l < L_SEQ) {
        const float* mrow = maskB + (size_t)l * L_SEQ;
#pragma unroll
        for (int j = 0; j < 8; j++) {
          int m = m0 + ((j < 4) ? (tx * 4 + j) : (64 + tx * 4 + (j - 4)));
          if (m < L_SEQ) {
            colsum[j] += tanhf(acc[i][j] * INV_TEMP) * mrow[m];
          }
        }
      }
    }
  }

  // Cross-thread reduction over the 16 ty-groups sharing each column.
#pragma unroll
  for (int j = 0; j < 8; j++) {
    int lc = (j < 4) ? (tx * 4 + j) : (64 + tx * 4 + (j - 4));
    As[ty][lc] = colsum[j];
  }
  __syncthreads();
  if (t < TM) {
    float s = 0.f;
#pragma unroll
    for (int r = 0; r < TK; r++) s += As[r][t];
    int m = m0 + t;
    if (m < L_SEQ) g_w[b * 704 + m] = s * (1.0f / 700.0f);
  }
}

// ---------------------------------------------------------------------------
// Kernel 2: one block per batch. One streaming pass over enc[b] computes both
// seq1[b,d] = sum_m w[b,m] enc[b,m,d]  and the three shifted c3-weighted row
// sums T[di][d]; then the 3x3 stencil gives seq2 and we emit
// tanh(user + seq1/2 + seq2*2).
// ---------------------------------------------------------------------------
__global__ __launch_bounds__(512) void finalize_kernel(
    const float* __restrict__ user, const float* __restrict__ enc,
    const float* __restrict__ conv_w, const float* __restrict__ conv_b,
    const float* __restrict__ conv3_w, const float* __restrict__ conv3_b,
    float* __restrict__ out) {
  const int b = blockIdx.x;
  const int d = threadIdx.x;  // 0..511

  __shared__ float sc3p[704];   // sc3p[0]=0, sc3p[1+h]=c3[h], tail zeros
  __shared__ float sw[704];
  __shared__ float T[3][514];   // padded stencil buffers (index d+1)

  for (int i = d; i < 704; i += 512) {
    sc3p[i] = 0.f;
    sw[i] = (i < L_SEQ) ? g_w[b * 704 + i] : 0.f;
  }
  __syncthreads();
  for (int i = d; i < L_SEQ; i += 512) sc3p[i + 1] = conv3_w[i];
  __syncthreads();

  // sum of c3 (for the conv_b pass-through term); 4-way partial to break the chain
  float cs0 = 0.f, cs1 = 0.f, cs2 = 0.f, cs3 = 0.f;
  for (int h = 0; h < L_SEQ; h += 4) {
    cs0 += sc3p[h + 1];
    cs1 += sc3p[h + 2];
    cs2 += sc3p[h + 3];
    cs3 += (h + 4 <= L_SEQ) ? sc3p[h + 4] : 0.f;
  }
  float c3sum = cs0 + cs1 + cs2 + cs3;

  const float* e = enc + (size_t)b * L_SEQ * D_DIM + d;
  float s1 = 0.f, tm1 = 0.f, t0 = 0.f, tp1 = 0.f;
#pragma unroll 4
  for (int h = 0; h < L_SEQ; h++) {
    float v = e[(size_t)h * D_DIM];
    s1  += sw[h] * v;
    tm1 += sc3p[h + 2] * v;   // c3[h+1]  (di = -1)
    t0  += sc3p[h + 1] * v;   // c3[h]    (di =  0)
    tp1 += sc3p[h]     * v;   // c3[h-1]  (di = +1)
  }

  T[0][d + 1] = tm1;
  T[1][d + 1] = t0;
  T[2][d + 1] = tp1;
  if (d == 0) {
    T[0][0] = 0.f; T[1][0] = 0.f; T[2][0] = 0.f;
    T[0][513] = 0.f; T[1][513] = 0.f; T[2][513] = 0.f;
  }
  __syncthreads();

  float W[3][3];
#pragma unroll
  for (int i = 0; i < 3; i++)
#pragma unroll
    for (int j = 0; j < 3; j++) W[i][j] = conv_w[i * 3 + j];

  float seq2 = conv3_b[0] + conv_b[0] * c3sum;
#pragma unroll
  for (int di = 0; di < 3; di++)
#pragma unroll
    for (int dj = 0; dj < 3; dj++)
      seq2 += W[di][dj] * T[di][d + dj];

  out[b * D_DIM + d] = tanhf(user[b * D_DIM + d] + s1 * 0.5f + seq2 * 2.0f);
}

extern "C" void kernel_launch(void* const* d_in, const int* in_sizes, int n_in,
                              void* d_out, int out_size) {
  const float* user    = (const float*)d_in[0];
  // d_in[1] = embeddings (22,512) — unused by the reference
  const float* enc     = (const float*)d_in[2];
  const float* mask    = (const float*)d_in[3];
  const float* conv_w  = (const float*)d_in[4];
  const float* conv_b  = (const float*)d_in[5];
  const float* conv3_w = (const float*)d_in[6];
  const float* conv3_b = (const float*)d_in[7];
  float* out = (float*)d_out;

  dim3 grid1((L_SEQ + TM - 1) / TM, B_SZ);   // (6, 64)
  attn_colsum_kernel<<<grid1, 256>>>(enc, mask);
  finalize_kernel<<<B_SZ, 512>>>(user, enc, conv_w, conv_b, conv3_w, conv3_b, out);
}

// round 4
// speedup vs baseline: 3.8241x; 3.8153x over previous
#include <cuda_runtime.h>
#include <cuda_bf16.h>
#include <cstdint>
#include <math.h>

#define L_SEQ 700
#define D_DIM 512
#define B_SZ  64
#define EX2_SCALE 0.12751742f   // 2*log2(e)/sqrt(512): tanh(G/sqrt(512)) = 1 - 2/(1+exp2(G*EX2_SCALE))

#define KCHUNK  32
#define NCHUNK  16              // 512 / 32
#define SROW    44              // smem row stride in floats: 16B-aligned, conflict-free frags
#define TILE_F  (128 * SROW)    // floats per 128x32 tile
#define SMEM_DYN (4 * TILE_F * 4)   // A/B double-buffered, bytes (90112)

// ---- scratch (device globals; allocation-free) -----------------------------
__device__ float g_encr[(size_t)B_SZ * L_SEQ * D_DIM];   // tf32-rounded enc
__device__ float g_wpart[6 * B_SZ * 704];                // [rowtile][b][m]
__device__ float g_part[(size_t)B_SZ * 4 * 4 * D_DIM];   // [b][hchunk][comp][d]

__device__ __forceinline__ uint32_t smem_u32(const void* p) {
  uint32_t a;
  asm("{ .reg .u64 t; cvta.to.shared.u64 t, %1; cvt.u32.u64 %0, t; }" : "=r"(a) : "l"(p));
  return a;
}
__device__ __forceinline__ void cp16(uint32_t dst, const void* src, bool pred) {
  int sz = pred ? 16 : 0;  // src-size 0 => zero-fill
  asm volatile("cp.async.cg.shared.global [%0], [%1], 16, %2;" :: "r"(dst), "l"(src), "r"(sz) : "memory");
}
__device__ __forceinline__ void mma1688(float* d, const float* a, const float* b) {
  asm volatile(
      "mma.sync.aligned.m16n8k8.row.col.f32.tf32.tf32.f32 "
      "{%0,%1,%2,%3}, {%4,%5,%6,%7}, {%8,%9}, {%0,%1,%2,%3};"
      : "+f"(d[0]), "+f"(d[1]), "+f"(d[2]), "+f"(d[3])
      : "r"(__float_as_uint(a[0])), "r"(__float_as_uint(a[1])),
        "r"(__float_as_uint(a[2])), "r"(__float_as_uint(a[3])),
        "r"(__float_as_uint(b[0])), "r"(__float_as_uint(b[1])));
}
__device__ __forceinline__ float fast_tanh_scaled(float g) {
  float e, r;
  asm("ex2.approx.f32 %0, %1;" : "=f"(e) : "f"(g * EX2_SCALE));
  asm("rcp.approx.f32 %0, %1;" : "=f"(r) : "f"(e + 1.0f));
  return fmaf(-2.0f, r, 1.0f);
}

// ---------------------------------------------------------------------------
// Kernel 0: round enc to tf32 (round-to-nearest) to kill truncation bias.
// ---------------------------------------------------------------------------
__global__ void preround_kernel(const float* __restrict__ enc) {
  size_t i = (size_t)blockIdx.x * blockDim.x + threadIdx.x;
  size_t n = (size_t)B_SZ * L_SEQ * D_DIM / 4;
  if (i < n) {
    float4 v = ((const float4*)enc)[i];
    uint32_t r;
    asm("cvt.rna.tf32.f32 %0, %1;" : "=r"(r) : "f"(v.x)); v.x = __uint_as_float(r);
    asm("cvt.rna.tf32.f32 %0, %1;" : "=r"(r) : "f"(v.y)); v.y = __uint_as_float(r);
    asm("cvt.rna.tf32.f32 %0, %1;" : "=r"(r) : "f"(v.z)); v.z = __uint_as_float(r);
    asm("cvt.rna.tf32.f32 %0, %1;" : "=r"(r) : "f"(v.w)); v.w = __uint_as_float(r);
    ((float4*)g_encr)[i] = v;
  }
}

// ---------------------------------------------------------------------------
// Kernel 1: mma.sync tf32 GEMM tile (128 l x 128 m) of G = E E^T, fused
// epilogue tanh(G/TEMP)*mask + column sums -> g_wpart[rowtile][b][m].
// 8 warps, each 32(l) x 64(m): 2 m16 x 8 n8 fragments.
// ---------------------------------------------------------------------------
__global__ __launch_bounds__(256, 2) void attn_w_kernel(const float* __restrict__ mask) {
  extern __shared__ float dynf[];
  __shared__ float R[4][128];

  const int ct = blockIdx.x, rt = blockIdx.y, b = blockIdx.z;
  const int m0 = ct * 128, l0 = rt * 128;
  const int t = threadIdx.x, w = t >> 5, lane = t & 31;
  const int g = lane >> 2, tg = lane & 3;
  const int wl = w >> 1, wm = w & 1;           // 4 l-strips x 2 m-halves
  const float* encB = g_encr + (size_t)b * L_SEQ * D_DIM;
  const float* maskB = mask + (size_t)b * L_SEQ * L_SEQ;

  float c[2][8][4];
#pragma unroll
  for (int mi = 0; mi < 2; mi++)
#pragma unroll
    for (int ni = 0; ni < 8; ni++)
#pragma unroll
      for (int j = 0; j < 4; j++) c[mi][ni][j] = 0.f;

  auto prefetch = [&](int kc) {
    const int stage = kc & 1;
    float* As = dynf + stage * TILE_F;
    float* Bs = dynf + 2 * TILE_F + stage * TILE_F;
#pragma unroll
    for (int i = 0; i < 4; i++) {
      int idx = t + i * 256;
      int row = idx >> 3, seg = idx & 7;
      int l = l0 + row;
      bool p = (l < L_SEQ);
      cp16(smem_u32(As + row * SROW + seg * 4),
           encB + (p ? ((size_t)l * D_DIM + kc * KCHUNK + seg * 4) : 0), p);
      int m = m0 + row;
      bool q = (m < L_SEQ);
      cp16(smem_u32(Bs + row * SROW + seg * 4),
           encB + (q ? ((size_t)m * D_DIM + kc * KCHUNK + seg * 4) : 0), q);
    }
    asm volatile("cp.async.commit_group;" ::: "memory");
  };

  prefetch(0);
  for (int k = 0; k < NCHUNK; k++) {
    if (k + 1 < NCHUNK) {
      prefetch(k + 1);
      asm volatile("cp.async.wait_group 1;" ::: "memory");
    } else {
      asm volatile("cp.async.wait_group 0;" ::: "memory");
    }
    __syncthreads();
    const int stage = k & 1;
    const float* As = dynf + stage * TILE_F;
    const float* Bs = dynf + 2 * TILE_F + stage * TILE_F;
#pragma unroll
    for (int ks = 0; ks < 4; ks++) {
      const int k0 = ks * 8;
      float a[2][4], bb[8][2];
#pragma unroll
      for (int mi = 0; mi < 2; mi++) {
        const float* ap = As + (wl * 32 + mi * 16 + g) * SROW + k0 + tg;
        a[mi][0] = ap[0];
        a[mi][1] = ap[8 * SROW];
        a[mi][2] = ap[4];
        a[mi][3] = ap[8 * SROW + 4];
      }
#pragma unroll
      for (int ni = 0; ni < 8; ni++) {
        const float* bp = Bs + (wm * 64 + ni * 8 + g) * SROW + k0 + tg;
        bb[ni][0] = bp[0];
        bb[ni][1] = bp[4];
      }
#pragma unroll
      for (int mi = 0; mi < 2; mi++)
#pragma unroll
        for (int ni = 0; ni < 8; ni++) mma1688(c[mi][ni], a[mi], bb[ni]);
    }
    __syncthreads();
  }

  // ---- epilogue: tanh * mask, column sums ----
  float colA[8], colB[8];
#pragma unroll
  for (int ni = 0; ni < 8; ni++) { colA[ni] = 0.f; colB[ni] = 0.f; }
#pragma unroll
  for (int mi = 0; mi < 2; mi++) {
    const int lr0 = l0 + wl * 32 + mi * 16 + g;
    const int lr1 = lr0 + 8;
    const bool v0 = lr0 < L_SEQ, v1 = lr1 < L_SEQ;
    const float* mrow0 = maskB + (size_t)lr0 * L_SEQ;
    const float* mrow1 = maskB + (size_t)lr1 * L_SEQ;
#pragma unroll
    for (int ni = 0; ni < 8; ni++) {
      const int mc = m0 + wm * 64 + ni * 8 + tg * 2;
      const bool vm = mc < L_SEQ;   // mc even -> mc+1 valid too when vm
      float2 mk0 = make_float2(0.f, 0.f), mk1 = make_float2(0.f, 0.f);
      if (v0 && vm) mk0 = *(const float2*)(mrow0 + mc);
      if (v1 && vm) mk1 = *(const float2*)(mrow1 + mc);
      const float* cc = c[mi][ni];
      colA[ni] += fast_tanh_scaled(cc[0]) * mk0.x + fast_tanh_scaled(cc[2]) * mk1.x;
      colB[ni] += fast_tanh_scaled(cc[1]) * mk0.y + fast_tanh_scaled(cc[3]) * mk1.y;
    }
  }
#pragma unroll
  for (int ni = 0; ni < 8; ni++) {
    float vA = colA[ni], vB = colB[ni];
    vA += __shfl_xor_sync(0xffffffffu, vA, 4);
    vA += __shfl_xor_sync(0xffffffffu, vA, 8);
    vA += __shfl_xor_sync(0xffffffffu, vA, 16);
    vB += __shfl_xor_sync(0xffffffffu, vB, 4);
    vB += __shfl_xor_sync(0xffffffffu, vB, 8);
    vB += __shfl_xor_sync(0xffffffffu, vB, 16);
    if (g == 0) {
      R[wl][wm * 64 + ni * 8 + tg * 2]     = vA;
      R[wl][wm * 64 + ni * 8 + tg * 2 + 1] = vB;
    }
  }
  __syncthreads();
  if (t < 128) {
    int m = m0 + t;
    if (m < L_SEQ)
      g_wpart[((size_t)rt * B_SZ + b) * 704 + m] = R[0][t] + R[1][t] + R[2][t] + R[3][t];
  }
}

// ---------------------------------------------------------------------------
// Kernel 2: per (batch, h-chunk) partials of seq1 and the 3 shifted c3 sums.
// ---------------------------------------------------------------------------
__global__ __launch_bounds__(512) void finalize_partial(const float* __restrict__ enc,
                                                        const float* __restrict__ conv3_w) {
  const int b = blockIdx.x, hc = blockIdx.y;
  const int h0 = hc * 175;
  const int d = threadIdx.x;
  __shared__ float swl[175];
  __shared__ float c3l[177];
  for (int i = d; i < 175; i += 512) {
    float s = 0.f;
#pragma unroll
    for (int rt = 0; rt < 6; rt++) s += g_wpart[((size_t)rt * B_SZ + b) * 704 + h0 + i];
    swl[i] = s * (1.0f / 700.0f);
  }
  for (int i = d; i < 177; i += 512) {
    int hh = h0 - 1 + i;
    c3l[i] = (hh >= 0 && hh < L_SEQ) ? conv3_w[hh] : 0.f;
  }
  __syncthreads();
  const float* e = enc + ((size_t)b * L_SEQ + h0) * D_DIM + d;
  float s1 = 0.f, tm1 = 0.f, t0 = 0.f, tp1 = 0.f;
#pragma unroll 5
  for (int i = 0; i < 175; i++) {
    float v = e[(size_t)i * D_DIM];
    s1  = fmaf(swl[i],     v, s1);
    tm1 = fmaf(c3l[i + 2], v, tm1);
    t0  = fmaf(c3l[i + 1], v, t0);
    tp1 = fmaf(c3l[i],     v, tp1);
  }
  size_t o = (((size_t)b * 4 + hc) * 4) * D_DIM + d;
  g_part[o] = s1; g_part[o + 512] = tm1; g_part[o + 1024] = t0; g_part[o + 1536] = tp1;
}

// ---------------------------------------------------------------------------
// Kernel 3: reduce h-chunks, 3x3 stencil, final tanh.
// ---------------------------------------------------------------------------
__global__ __launch_bounds__(512) void finalize_reduce(
    const float* __restrict__ user, const float* __restrict__ conv_w,
    const float* __restrict__ conv_b, const float* __restrict__ conv3_w,
    const float* __restrict__ conv3_b, float* __restrict__ out) {
  const int b = blockIdx.x, d = threadIdx.x;
  __shared__ float T[3][514];
  __shared__ float red[512];
  float s1 = 0.f, tm1 = 0.f, t0 = 0.f, tp1 = 0.f;
#pragma unroll
  for (int hc = 0; hc < 4; hc++) {
    size_t o = (((size_t)b * 4 + hc) * 4) * D_DIM + d;
    s1 += g_part[o]; tm1 += g_part[o + 512]; t0 += g_part[o + 1024]; tp1 += g_part[o + 1536];
  }
  T[0][d + 1] = tm1; T[1][d + 1] = t0; T[2][d + 1] = tp1;
  if (d == 0) {
#pragma unroll
    for (int i = 0; i < 3; i++) { T[i][0] = 0.f; T[i][513] = 0.f; }
  }
  float cw = conv3_w[d];
  if (d + 512 < L_SEQ) cw += conv3_w[d + 512];
  red[d] = cw;
  __syncthreads();
  for (int sft = 256; sft > 0; sft >>= 1) {
    if (d < sft) red[d] += red[d + sft];
    __syncthreads();
  }
  const float c3sum = red[0];
  float seq2 = conv3_b[0] + conv_b[0] * c3sum;
#pragma unroll
  for (int di = 0; di < 3; di++)
#pragma unroll
    for (int dj = 0; dj < 3; dj++)
      seq2 = fmaf(conv_w[di * 3 + dj], T[di][d + dj], seq2);
  out[b * D_DIM + d] = tanhf(user[b * D_DIM + d] + s1 * 0.5f + seq2 * 2.0f);
}

extern "C" void kernel_launch(void* const* d_in, const int* in_sizes, int n_in,
                              void* d_out, int out_size) {
  const float* user    = (const float*)d_in[0];
  // d_in[1] = embeddings (22,512) — unused by the reference
  const float* enc     = (const float*)d_in[2];
  const float* mask    = (const float*)d_in[3];
  const float* conv_w  = (const float*)d_in[4];
  const float* conv_b  = (const float*)d_in[5];
  const float* conv3_w = (const float*)d_in[6];
  const float* conv3_b = (const float*)d_in[7];
  float* out = (float*)d_out;

  cudaFuncSetAttribute(attn_w_kernel, cudaFuncAttributeMaxDynamicSharedMemorySize, SMEM_DYN);

  size_t n4 = (size_t)B_SZ * L_SEQ * D_DIM / 4;
  preround_kernel<<<(unsigned)((n4 + 255) / 256), 256>>>(enc);
  attn_w_kernel<<<dim3(6, 6, B_SZ), 256, SMEM_DYN>>>(mask);
  finalize_partial<<<dim3(B_SZ, 4), 512>>>(enc, conv3_w);
  finalize_reduce<<<B_SZ, 512>>>(user, conv_w, conv_b, conv3_w, conv3_b, out);
}

// round 6
// speedup vs baseline: 7.1668x; 1.8741x over previous
#include <cuda_runtime.h>
#include <cuda_bf16.h>
#include <cstdint>
#include <math.h>

#define L_SEQ 700
#define D_DIM 512
#define B_SZ  64
#define EX2_SCALE 0.12751742f   // 2*log2(e)/sqrt(512): tanh(G/sqrt(512)) = 1 - 2/(1+exp2(G*EX2_SCALE))

#define KCHUNK  64              // bf16 elems per k-chunk (128B rows)
#define NCHUNK  8               // 512 / 64
#define STAGE_BYTES 16384       // 128 rows x 128B
#define SMEM_DYN (4 * STAGE_BYTES + 1024)

// ---- scratch (device globals; allocation-free) -----------------------------
__device__ __nv_bfloat16 g_encb[(size_t)B_SZ * L_SEQ * D_DIM];  // bf16 enc
__device__ float g_wpart[6 * B_SZ * 704];                // [rowtile][b][m]
__device__ float g_part[(size_t)B_SZ * 4 * 4 * D_DIM];   // [b][hchunk][comp][d]

__device__ __forceinline__ uint32_t smem_u32(const void* p) {
  uint32_t a;
  asm("{ .reg .u64 t; cvta.to.shared.u64 t, %1; cvt.u32.u64 %0, t; }" : "=r"(a) : "l"(p));
  return a;
}
__device__ __forceinline__ uint32_t pack_bf16x2(float lo, float hi) {
  uint32_t r;
  asm("cvt.rn.bf16x2.f32 %0, %1, %2;" : "=r"(r) : "f"(hi), "f"(lo));
  return r;
}
__device__ __forceinline__ void cp16(uint32_t dst, const void* src, bool pred) {
  int sz = pred ? 16 : 0;  // src-size 0 => zero-fill
  asm volatile("cp.async.cg.shared.global [%0], [%1], 16, %2;" :: "r"(dst), "l"(src), "r"(sz) : "memory");
}
__device__ __forceinline__ void ldsm_x4(uint32_t* r, uint32_t addr) {
  asm volatile("ldmatrix.sync.aligned.m8n8.x4.shared.b16 {%0,%1,%2,%3}, [%4];"
               : "=r"(r[0]), "=r"(r[1]), "=r"(r[2]), "=r"(r[3]) : "r"(addr));
}
__device__ __forceinline__ void mma16816(float* d, const uint32_t* a, const uint32_t* b) {
  asm volatile(
      "mma.sync.aligned.m16n8k16.row.col.f32.bf16.bf16.f32 "
      "{%0,%1,%2,%3}, {%4,%5,%6,%7}, {%8,%9}, {%0,%1,%2,%3};"
      : "+f"(d[0]), "+f"(d[1]), "+f"(d[2]), "+f"(d[3])
      : "r"(a[0]), "r"(a[1]), "r"(a[2]), "r"(a[3]), "r"(b[0]), "r"(b[1]));
}
__device__ __forceinline__ float fast_tanh_scaled(float g) {
  float e, r;
  asm("ex2.approx.f32 %0, %1;" : "=f"(e) : "f"(g * EX2_SCALE));
  asm("rcp.approx.f32 %0, %1;" : "=f"(r) : "f"(e + 1.0f));
  return fmaf(-2.0f, r, 1.0f);
}
#define SWZ(b) ((b) ^ (((b) >> 3) & 0x70))

// ---------------------------------------------------------------------------
// Kernel 0: convert enc to bf16 (round-to-nearest).
// ---------------------------------------------------------------------------
__global__ void tobf16_kernel(const float* __restrict__ enc) {
  size_t i = (size_t)blockIdx.x * blockDim.x + threadIdx.x;
  size_t n = (size_t)B_SZ * L_SEQ * D_DIM / 8;
  if (i < n) {
    float4 v0 = ((const float4*)enc)[2 * i];
    float4 v1 = ((const float4*)enc)[2 * i + 1];
    uint4 o;
    o.x = pack_bf16x2(v0.x, v0.y);
    o.y = pack_bf16x2(v0.z, v0.w);
    o.z = pack_bf16x2(v1.x, v1.y);
    o.w = pack_bf16x2(v1.z, v1.w);
    ((uint4*)g_encb)[i] = o;
  }
}

// ---------------------------------------------------------------------------
// Kernel 1: bf16 mma.sync GEMM tile (128 l x 128 m) of G = E E^T, fused
// epilogue tanh(G/TEMP)*mask + column sums -> g_wpart[rowtile][b][m].
// 8 warps, each 32(l) x 64(m). ldmatrix.x4 operand loads, XOR-swizzled smem.
// ---------------------------------------------------------------------------
__global__ __launch_bounds__(256) void attn_w_kernel(const float* __restrict__ mask) {
  extern __shared__ char dynraw[];
  char* dynbase = (char*)(((uintptr_t)dynraw + 1023) & ~(uintptr_t)1023);
  const uint32_t sb = smem_u32(dynbase);
  __shared__ float R[4][128];

  const int ct = blockIdx.x, rt = blockIdx.y, b = blockIdx.z;
  const int m0 = ct * 128, l0 = rt * 128;
  const int t = threadIdx.x, w = t >> 5, lane = t & 31;
  const int g = lane >> 2, tg = lane & 3;
  const int wl = w >> 1, wm = w & 1;           // 4 l-strips x 2 m-halves
  const __nv_bfloat16* encB = g_encb + (size_t)b * L_SEQ * D_DIM;
  const float* maskB = mask + (size_t)b * L_SEQ * L_SEQ;

  // ldmatrix per-lane address pieces (offsets within a stage tile)
  const int tile = lane >> 3, trow = lane & 7;
  uint32_t aRB[2], aM[2];
#pragma unroll
  for (int mi = 0; mi < 2; mi++) {
    int row = wl * 32 + mi * 16 + (tile & 1) * 8 + trow;
    aRB[mi] = (uint32_t)(row << 7);
    aM[mi]  = (uint32_t)((row & 7) << 4);
  }
  const uint32_t kaoff = (uint32_t)((tile >> 1) << 4);   // A kgroup*16
  uint32_t bRB[4], bM[4];
#pragma unroll
  for (int p = 0; p < 4; p++) {
    int row = wm * 64 + p * 16 + (tile >> 1) * 8 + trow;
    bRB[p] = (uint32_t)(row << 7);
    bM[p]  = (uint32_t)((row & 7) << 4);
  }
  const uint32_t kboff = (uint32_t)((tile & 1) << 4);    // B kgroup*16

  float c[2][8][4];
#pragma unroll
  for (int mi = 0; mi < 2; mi++)
#pragma unroll
    for (int ni = 0; ni < 8; ni++)
#pragma unroll
      for (int j = 0; j < 4; j++) c[mi][ni][j] = 0.f;

  auto prefetch = [&](int kc) {
    const int stage = kc & 1;
    const uint32_t As = sb + stage * STAGE_BYTES;
    const uint32_t Bs = sb + 2 * STAGE_BYTES + stage * STAGE_BYTES;
#pragma unroll
    for (int i = 0; i < 4; i++) {
      int idx = t + i * 256;
      int row = idx >> 3, seg = idx & 7;
      int l = l0 + row;
      bool p = (l < L_SEQ);
      cp16(As + SWZ(row * 128 + seg * 16),
           encB + (p ? ((size_t)l * D_DIM + kc * KCHUNK + seg * 8) : 0), p);
      int m = m0 + row;
      bool q = (m < L_SEQ);
      cp16(Bs + SWZ(row * 128 + seg * 16),
           encB + (q ? ((size_t)m * D_DIM + kc * KCHUNK + seg * 8) : 0), q);
    }
    asm volatile("cp.async.commit_group;" ::: "memory");
  };

  prefetch(0);
  for (int k = 0; k < NCHUNK; k++) {
    if (k + 1 < NCHUNK) {
      prefetch(k + 1);
      asm volatile("cp.async.wait_group 1;" ::: "memory");
    } else {
      asm volatile("cp.async.wait_group 0;" ::: "memory");
    }
    __syncthreads();
    const int stage = k & 1;
    const uint32_t As = sb + stage * STAGE_BYTES;
    const uint32_t Bs = sb + 2 * STAGE_BYTES + stage * STAGE_BYTES;
#pragma unroll
    for (int ks = 0; ks < 4; ks++) {
      const uint32_t ko = (uint32_t)(ks << 5);
      uint32_t a[2][4], bfr[4][4];
#pragma unroll
      for (int mi = 0; mi < 2; mi++)
        ldsm_x4(a[mi], As + aRB[mi] + ((ko + kaoff) ^ aM[mi]));
#pragma unroll
      for (int p = 0; p < 4; p++)
        ldsm_x4(bfr[p], Bs + bRB[p] + ((ko + kboff) ^ bM[p]));
#pragma unroll
      for (int mi = 0; mi < 2; mi++)
#pragma unroll
        for (int p = 0; p < 4; p++) {
          mma16816(c[mi][2 * p],     a[mi], &bfr[p][0]);
          mma16816(c[mi][2 * p + 1], a[mi], &bfr[p][2]);
        }
    }
    __syncthreads();
  }

  // ---- epilogue: tanh * mask, column sums ----
  float colA[8], colB[8];
#pragma unroll
  for (int ni = 0; ni < 8; ni++) { colA[ni] = 0.f; colB[ni] = 0.f; }
#pragma unroll
  for (int mi = 0; mi < 2; mi++) {
    const int lr0 = l0 + wl * 32 + mi * 16 + g;
    const int lr1 = lr0 + 8;
    const bool v0 = lr0 < L_SEQ, v1 = lr1 < L_SEQ;
    const float* mrow0 = maskB + (size_t)lr0 * L_SEQ;
    const float* mrow1 = maskB + (size_t)lr1 * L_SEQ;
#pragma unroll
    for (int ni = 0; ni < 8; ni++) {
      const int mc = m0 + wm * 64 + ni * 8 + tg * 2;
      const bool vm = mc < L_SEQ;   // mc even -> mc+1 valid too when vm
      float2 mk0 = make_float2(0.f, 0.f), mk1 = make_float2(0.f, 0.f);
      if (v0 && vm) mk0 = *(const float2*)(mrow0 + mc);
      if (v1 && vm) mk1 = *(const float2*)(mrow1 + mc);
      const float* cc = c[mi][ni];
      colA[ni] += fast_tanh_scaled(cc[0]) * mk0.x + fast_tanh_scaled(cc[2]) * mk1.x;
      colB[ni] += fast_tanh_scaled(cc[1]) * mk0.y + fast_tanh_scaled(cc[3]) * mk1.y;
    }
  }
#pragma unroll
  for (int ni = 0; ni < 8; ni++) {
    float vA = colA[ni], vB = colB[ni];
    vA += __shfl_xor_sync(0xffffffffu, vA, 4);
    vA += __shfl_xor_sync(0xffffffffu, vA, 8);
    vA += __shfl_xor_sync(0xffffffffu, vA, 16);
    vB += __shfl_xor_sync(0xffffffffu, vB, 4);
    vB += __shfl_xor_sync(0xffffffffu, vB, 8);
    vB += __shfl_xor_sync(0xffffffffu, vB, 16);
    if (g == 0) {
      R[wl][wm * 64 + ni * 8 + tg * 2]     = vA;
      R[wl][wm * 64 + ni * 8 + tg * 2 + 1] = vB;
    }
  }
  __syncthreads();
  if (t < 128) {
    int m = m0 + t;
    if (m < L_SEQ)
      g_wpart[((size_t)rt * B_SZ + b) * 704 + m] = R[0][t] + R[1][t] + R[2][t] + R[3][t];
  }
}

// ---------------------------------------------------------------------------
// Kernel 2: per (batch, h-chunk) partials of seq1 and the 3 shifted c3 sums.
// ---------------------------------------------------------------------------
__global__ __launch_bounds__(512) void finalize_partial(const float* __restrict__ enc,
                                                        const float* __restrict__ conv3_w) {
  const int b = blockIdx.x, hc = blockIdx.y;
  const int h0 = hc * 175;
  const int d = threadIdx.x;
  __shared__ float swl[175];
  __shared__ float c3l[177];
  for (int i = d; i < 175; i += 512) {
    float s = 0.f;
#pragma unroll
    for (int rt = 0; rt < 6; rt++) s += g_wpart[((size_t)rt * B_SZ + b) * 704 + h0 + i];
    swl[i] = s * (1.0f / 700.0f);
  }
  for (int i = d; i < 177; i += 512) {
    int hh = h0 - 1 + i;
    c3l[i] = (hh >= 0 && hh < L_SEQ) ? conv3_w[hh] : 0.f;
  }
  __syncthreads();
  const float* e = enc + ((size_t)b * L_SEQ + h0) * D_DIM + d;
  float s1 = 0.f, tm1 = 0.f, t0 = 0.f, tp1 = 0.f;
#pragma unroll 5
  for (int i = 0; i < 175; i++) {
    float v = e[(size_t)i * D_DIM];
    s1  = fmaf(swl[i],     v, s1);
    tm1 = fmaf(c3l[i + 2], v, tm1);
    t0  = fmaf(c3l[i + 1], v, t0);
    tp1 = fmaf(c3l[i],     v, tp1);
  }
  size_t o = (((size_t)b * 4 + hc) * 4) * D_DIM + d;
  g_part[o] = s1; g_part[o + 512] = tm1; g_part[o + 1024] = t0; g_part[o + 1536] = tp1;
}

// ---------------------------------------------------------------------------
// Kernel 3: reduce h-chunks, 3x3 stencil, final tanh.
// ---------------------------------------------------------------------------
__global__ __launch_bounds__(512) void finalize_reduce(
    const float* __restrict__ user, const float* __restrict__ conv_w,
    const float* __restrict__ conv_b, const float* __restrict__ conv3_w,
    const float* __restrict__ conv3_b, float* __restrict__ out) {
  const int b = blockIdx.x, d = threadIdx.x;
  __shared__ float T[3][514];
  __shared__ float red[512];
  float s1 = 0.f, tm1 = 0.f, t0 = 0.f, tp1 = 0.f;
#pragma unroll
  for (int hc = 0; hc < 4; hc++) {
    size_t o = (((size_t)b * 4 + hc) * 4) * D_DIM + d;
    s1 += g_part[o]; tm1 += g_part[o + 512]; t0 += g_part[o + 1024]; tp1 += g_part[o + 1536];
  }
  T[0][d + 1] = tm1; T[1][d + 1] = t0; T[2][d + 1] = tp1;
  if (d == 0) {
#pragma unroll
    for (int i = 0; i < 3; i++) { T[i][0] = 0.f; T[i][513] = 0.f; }
  }
  float cw = conv3_w[d];
  if (d + 512 < L_SEQ) cw += conv3_w[d + 512];
  red[d] = cw;
  __syncthreads();
  for (int sft = 256; sft > 0; sft >>= 1) {
    if (d < sft) red[d] += red[d + sft];
    __syncthreads();
  }
  const float c3sum = red[0];
  float seq2 = conv3_b[0] + conv_b[0] * c3sum;
#pragma unroll
  for (int di = 0; di < 3; di++)
#pragma unroll
    for (int dj = 0; dj < 3; dj++)
      seq2 = fmaf(conv_w[di * 3 + dj], T[di][d + dj], seq2);
  out[b * D_DIM + d] = tanhf(user[b * D_DIM + d] + s1 * 0.5f + seq2 * 2.0f);
}

extern "C" void kernel_launch(void* const* d_in, const int* in_sizes, int n_in,
                              void* d_out, int out_size) {
  const float* user    = (const float*)d_in[0];
  // d_in[1] = embeddings (22,512) — unused by the reference
  const float* enc     = (const float*)d_in[2];
  const float* mask    = (const float*)d_in[3];
  const float* conv_w  = (const float*)d_in[4];
  const float* conv_b  = (const float*)d_in[5];
  const float* conv3_w = (const float*)d_in[6];
  const float* conv3_b = (const float*)d_in[7];
  float* out = (float*)d_out;

  cudaFuncSetAttribute(attn_w_kernel, cudaFuncAttributeMaxDynamicSharedMemorySize, SMEM_DYN);

  size_t n8 = (size_t)B_SZ * L_SEQ * D_DIM / 8;
  tobf16_kernel<<<(unsigned)((n8 + 255) / 256), 256>>>(enc);
  attn_w_kernel<<<dim3(6, 6, B_SZ), 256, SMEM_DYN>>>(mask);
  finalize_partial<<<dim3(B_SZ, 4), 512>>>(enc, conv3_w);
  finalize_reduce<<<B_SZ, 512>>>(user, conv_w, conv_b, conv3_w, conv3_b, out);
}